// round 1
// baseline (speedup 1.0000x reference)
#include <cuda_runtime.h>
#include <math.h>
#include <stdint.h>

// ----------------------------------------------------------------------------
// QuantizedSSM: x_next = q8(x @ Aq^T + u @ Bq^T); y = q8(x_next @ Cq^T)
// Shapes: x(4096,2048) u(4096,1024) A(2048,2048) B(2048,1024) C(1024,2048)
// Output: [x_next (4096*2048) | y (4096*1024)] fp32
// ----------------------------------------------------------------------------

#define MDIM 4096
#define NDIM 2048   // n
#define MMID 1024   // m (and p)

// Static device scratch for quantized matrices (allocation-free rule)
__device__ float g_Aq[(size_t)NDIM * NDIM];   // 16 MB
__device__ float g_Bq[(size_t)NDIM * MMID];   //  8 MB
__device__ float g_Cq[(size_t)MMID * NDIM];   //  8 MB

// to_float8(x, exp_bits=4, mant_bits=3) replica.
// exp = clip(floor(log2(|x|+1e-8)), -7, 7); mant_q = rint((|x|/2^exp - 1)*8)/8
// result = sign * (1 + mant_q) * 2^exp   (sign(0) = 0)
__device__ __forceinline__ float q8(float v) {
    float a = fabsf(v);
    float s = (v > 0.0f) ? 1.0f : ((v < 0.0f) ? -1.0f : 0.0f);
    float e = floorf(log2f(a + 1e-8f));
    e = fminf(fmaxf(e, -7.0f), 7.0f);
    float p = exp2f(e);
    float m = a / p - 1.0f;
    float mq = rintf(m * 8.0f) * 0.125f;   // rint = round-half-to-even, matches jnp.round
    return s * (1.0f + mq) * p;
}

__global__ void quant_kernel(const float* __restrict__ in, float* __restrict__ out, int n) {
    int i = blockIdx.x * blockDim.x + threadIdx.x;
    if (i < n) out[i] = q8(in[i]);
}

// ----------------------------------------------------------------------------
// NT GEMM: C[i,j] (+)= sum_k Ag[i,k] * Bg[j,k]
// Ag: M x K row-major, Bg: N x K row-major, C: M x N row-major
// BM=BN=128, BK=8, 256 threads, 8x8 per-thread microtile.
// M,N multiples of 128; K multiple of 8 (true for all three calls).
// ----------------------------------------------------------------------------
#define BM 128
#define BN 128
#define BK 8
#define TM 8
#define TN 8

template <bool ACC, bool QUANT>
__global__ void __launch_bounds__(256, 2)
gemm_nt(const float* __restrict__ Ag, const float* __restrict__ Bg,
        float* __restrict__ Cg, int M, int N, int K)
{
    __shared__ float As[BK][BM];
    __shared__ float Bs[BK][BN];

    const int bm = blockIdx.y * BM;
    const int bn = blockIdx.x * BN;
    const int tid = threadIdx.x;
    const int tx = tid & 15;     // 0..15 -> N direction
    const int ty = tid >> 4;     // 0..15 -> M direction

    // Global load mapping: each thread loads one float4 per operand per k-tile.
    const int lr = tid >> 1;          // 0..127  (row within tile)
    const int lc = (tid & 1) * 4;     // 0 or 4  (col within 8-wide k-slab)

    const float* Aptr = Ag + (size_t)(bm + lr) * K + lc;
    const float* Bptr = Bg + (size_t)(bn + lr) * K + lc;

    float acc[TM][TN];
#pragma unroll
    for (int i = 0; i < TM; i++)
#pragma unroll
        for (int j = 0; j < TN; j++) acc[i][j] = 0.0f;

    for (int k0 = 0; k0 < K; k0 += BK) {
        float4 av = *reinterpret_cast<const float4*>(Aptr + k0);
        float4 bv = *reinterpret_cast<const float4*>(Bptr + k0);
        As[lc + 0][lr] = av.x; As[lc + 1][lr] = av.y;
        As[lc + 2][lr] = av.z; As[lc + 3][lr] = av.w;
        Bs[lc + 0][lr] = bv.x; Bs[lc + 1][lr] = bv.y;
        Bs[lc + 2][lr] = bv.z; Bs[lc + 3][lr] = bv.w;
        __syncthreads();

#pragma unroll
        for (int k = 0; k < BK; k++) {
            float ar[TM], br[TN];
            float4 a0 = *reinterpret_cast<const float4*>(&As[k][ty * TM]);
            float4 a1 = *reinterpret_cast<const float4*>(&As[k][ty * TM + 4]);
            float4 b0 = *reinterpret_cast<const float4*>(&Bs[k][tx * TN]);
            float4 b1 = *reinterpret_cast<const float4*>(&Bs[k][tx * TN + 4]);
            ar[0]=a0.x; ar[1]=a0.y; ar[2]=a0.z; ar[3]=a0.w;
            ar[4]=a1.x; ar[5]=a1.y; ar[6]=a1.z; ar[7]=a1.w;
            br[0]=b0.x; br[1]=b0.y; br[2]=b0.z; br[3]=b0.w;
            br[4]=b1.x; br[5]=b1.y; br[6]=b1.z; br[7]=b1.w;
#pragma unroll
            for (int i = 0; i < TM; i++)
#pragma unroll
                for (int j = 0; j < TN; j++)
                    acc[i][j] = fmaf(ar[i], br[j], acc[i][j]);
        }
        __syncthreads();
    }

    // Epilogue: optional accumulate with existing C, optional quantization.
#pragma unroll
    for (int i = 0; i < TM; i++) {
        const size_t row = (size_t)(bm + ty * TM + i);
        float* crow = Cg + row * N + bn + tx * TN;
#pragma unroll
        for (int jv = 0; jv < 2; jv++) {
            float4 v = *reinterpret_cast<float4*>(&acc[i][jv * 4]);
            if (ACC) {
                float4 c = *reinterpret_cast<const float4*>(crow + jv * 4);
                v.x += c.x; v.y += c.y; v.z += c.z; v.w += c.w;
            }
            if (QUANT) {
                v.x = q8(v.x); v.y = q8(v.y); v.z = q8(v.z); v.w = q8(v.w);
            }
            *reinterpret_cast<float4*>(crow + jv * 4) = v;
        }
    }
}

extern "C" void kernel_launch(void* const* d_in, const int* in_sizes, int n_in,
                              void* d_out, int out_size)
{
    const float* x = (const float*)d_in[0];   // 4096 x 2048
    const float* u = (const float*)d_in[1];   // 4096 x 1024
    const float* A = (const float*)d_in[2];   // 2048 x 2048
    const float* B = (const float*)d_in[3];   // 2048 x 1024
    const float* C = (const float*)d_in[4];   // 1024 x 2048

    float* out    = (float*)d_out;
    float* x_next = out;                                   // 4096*2048
    float* y      = out + (size_t)MDIM * NDIM;             // 4096*1024

    float *Aq, *Bq, *Cq;
    cudaGetSymbolAddress((void**)&Aq, g_Aq);
    cudaGetSymbolAddress((void**)&Bq, g_Bq);
    cudaGetSymbolAddress((void**)&Cq, g_Cq);

    // 1) Quantize A, B, C
    {
        const int T = 256;
        int nA = NDIM * NDIM, nB = NDIM * MMID, nC = MMID * NDIM;
        quant_kernel<<<(nA + T - 1) / T, T>>>(A, Aq, nA);
        quant_kernel<<<(nB + T - 1) / T, T>>>(B, Bq, nB);
        quant_kernel<<<(nC + T - 1) / T, T>>>(C, Cq, nC);
    }

    dim3 block(256);

    // 2) out = x @ Aq^T           (M=4096, N=2048, K=2048)
    {
        dim3 grid(NDIM / BN, MDIM / BM);
        gemm_nt<false, false><<<grid, block>>>(x, Aq, x_next, MDIM, NDIM, NDIM);
    }
    // 3) x_next = q8(out + u @ Bq^T)   (M=4096, N=2048, K=1024)
    {
        dim3 grid(NDIM / BN, MDIM / BM);
        gemm_nt<true, true><<<grid, block>>>(u, Bq, x_next, MDIM, NDIM, MMID);
    }
    // 4) y = q8(x_next @ Cq^T)    (M=4096, N=1024, K=2048)
    {
        dim3 grid(MMID / BN, MDIM / BM);
        gemm_nt<false, true><<<grid, block>>>(x_next, Cq, y, MDIM, MMID, NDIM);
    }
}

// round 5
// speedup vs baseline: 3.2057x; 3.2057x over previous
#include <cuda_runtime.h>
#include <cuda_fp16.h>
#include <math.h>
#include <stdint.h>

// ============================================================================
// QuantizedSSM via mma.sync (HMMA) with chunked fp32 re-accumulation.
// HMMA's internal accumulation rounds toward zero -> linear bias over long
// chains. We flush the HMMA accumulator into a master fp32 accumulator (RN)
// every 4 chunks (256 k-elements) to keep fp32-class accuracy.
//   x_next = q8( x @ Aq^T + u @ Bq^T ) : fused fp16 GEMM, K = 6144
//   y      = q8( x_next @ Cq^T )       : exact fp16 GEMM, K = 2048
// ============================================================================

#define MDIM 4096
#define NDIM 2048
#define MMID 1024
#define KEFF (2*NDIM + 2*MMID)   // 6144

__device__ __half g_Aq [(size_t)NDIM * NDIM];
__device__ __half g_Aq2[(size_t)NDIM * NDIM];   // Aq / 64
__device__ __half g_Bq [(size_t)NDIM * MMID];
__device__ __half g_Bq2[(size_t)NDIM * MMID];   // Bq / 64
__device__ __half g_Cq [(size_t)MMID * NDIM];
__device__ __half g_XU [(size_t)MDIM * KEFF];   // [x1 | x2*64 | u1 | u2*64]
__device__ __half g_Xn [(size_t)MDIM * NDIM];   // x_next fp16 (exact)

// ----------------------------------------------------------------------------
// q8 = to_float8(v, 4, 3), branch-free bit version (exact vs reference).
// ----------------------------------------------------------------------------
__device__ __forceinline__ float q8(float v) {
    float a  = fabsf(v);
    float ae = a + 1e-8f;
    int e = ((__float_as_int(ae) >> 23) & 0xFF) - 127;
    e = min(max(e, -7), 7);
    float p  = __int_as_float((e + 127) << 23);   // 2^e
    float rp = __int_as_float((127 - e) << 23);   // 2^-e (exact)
    float m  = fmaf(a, rp, -1.0f);
    float mq = rintf(m * 8.0f);                   // round-half-even == jnp.round
    float r  = fmaf(mq, 0.125f, 1.0f) * p;
    return (v > 0.0f) ? r : ((v < 0.0f) ? -r : 0.0f);
}

// ----------------------------------------------------------------------------
// PTX helpers — all plain-target (sm_80+) instructions
// ----------------------------------------------------------------------------
__device__ __forceinline__ uint32_t smem_u32(const void* p) {
    uint32_t a;
    asm("{ .reg .u64 t; cvta.to.shared.u64 t, %1; cvt.u32.u64 %0, t; }"
        : "=r"(a) : "l"(p));
    return a;
}
__device__ __forceinline__ void cp16(uint32_t dst, const void* src) {
    asm volatile("cp.async.cg.shared.global [%0], [%1], 16;"
                 :: "r"(dst), "l"(src) : "memory");
}
__device__ __forceinline__ void cp_commit() {
    asm volatile("cp.async.commit_group;" ::: "memory");
}
__device__ __forceinline__ void ldsm4(uint32_t& r0, uint32_t& r1, uint32_t& r2,
                                      uint32_t& r3, uint32_t addr) {
    asm volatile("ldmatrix.sync.aligned.m8n8.x4.shared.b16 {%0,%1,%2,%3}, [%4];"
                 : "=r"(r0), "=r"(r1), "=r"(r2), "=r"(r3) : "r"(addr));
}
__device__ __forceinline__ void mma16816(float* d, const uint32_t* a, const uint32_t* b) {
    asm volatile(
        "mma.sync.aligned.m16n8k16.row.col.f32.f16.f16.f32 "
        "{%0,%1,%2,%3}, {%4,%5,%6,%7}, {%8,%9}, {%0,%1,%2,%3};"
        : "+f"(d[0]), "+f"(d[1]), "+f"(d[2]), "+f"(d[3])
        : "r"(a[0]), "r"(a[1]), "r"(a[2]), "r"(a[3]), "r"(b[0]), "r"(b[1]));
}

// SW128 swizzle (Swizzle<3,4,3>) on byte offsets within a tile (128B rows)
__device__ __forceinline__ uint32_t swz(uint32_t o) { return o ^ ((o >> 3) & 0x70); }

// ----------------------------------------------------------------------------
// Prep kernels
// ----------------------------------------------------------------------------
__global__ void quantq(const float* __restrict__ in, __half* __restrict__ out,
                       __half* __restrict__ out2, int n) {
    size_t i = ((size_t)blockIdx.x * blockDim.x + threadIdx.x) * 4;
    if (i >= (size_t)n) return;
    float4 v = *reinterpret_cast<const float4*>(in + i);
    float q0 = q8(v.x), q1 = q8(v.y), q2 = q8(v.z), q3 = q8(v.w);
    __half2 p0 = __floats2half2_rn(q0, q1);
    __half2 p1 = __floats2half2_rn(q2, q3);
    uint2 pk;
    pk.x = *reinterpret_cast<uint32_t*>(&p0);
    pk.y = *reinterpret_cast<uint32_t*>(&p1);
    *reinterpret_cast<uint2*>(out + i) = pk;
    if (out2) {
        const float s = 0.015625f;  // 1/64, exact scaling
        __half2 s0 = __floats2half2_rn(q0 * s, q1 * s);
        __half2 s1 = __floats2half2_rn(q2 * s, q3 * s);
        uint2 sk;
        sk.x = *reinterpret_cast<uint32_t*>(&s0);
        sk.y = *reinterpret_cast<uint32_t*>(&s1);
        *reinterpret_cast<uint2*>(out2 + i) = sk;
    }
}

// split fp32 -> plane1 = fp16(v) at [col], plane2 = fp16((v-plane1)*64) at [col+cols]
__global__ void splitk(const float* __restrict__ src, int cols, __half* __restrict__ dst) {
    size_t idx = (size_t)blockIdx.x * blockDim.x + threadIdx.x;
    size_t i4 = idx * 4;
    if (i4 >= (size_t)MDIM * cols) return;
    int row = (int)(i4 / cols);
    int col = (int)(i4 % cols);
    float4 v = *reinterpret_cast<const float4*>(src + i4);
    float f[4] = {v.x, v.y, v.z, v.w};
    __half h1[4], h2[4];
#pragma unroll
    for (int j = 0; j < 4; j++) {
        __half b1 = __float2half_rn(f[j]);
        float r1 = f[j] - __half2float(b1);   // exact in fp32
        h1[j] = b1;
        h2[j] = __float2half_rn(r1 * 64.0f);  // scaled into normal fp16 range
    }
    __half* d0 = dst + (size_t)row * KEFF + col;
    auto pack = [](__half* h) {
        __half2 p0(h[0], h[1]), p1(h[2], h[3]);
        uint2 r;
        r.x = *reinterpret_cast<uint32_t*>(&p0);
        r.y = *reinterpret_cast<uint32_t*>(&p1);
        return r;
    };
    *reinterpret_cast<uint2*>(d0)        = pack(h1);
    *reinterpret_cast<uint2*>(d0 + cols) = pack(h2);
}

// ----------------------------------------------------------------------------
// HMMA GEMM-NT, 128x128 CTA tile, BK=64, 3-stage cp.async pipeline.
// HMMA accumulator is flushed into a master fp32 accumulator every 4 chunks.
// MODE 0 (fused GEMM1): chunk c -> B segment
//   c in [ 0,32): Aq   col (c&31)*64, ld NDIM   (pairs x plane1)
//   c in [32,64): Aq2  col (c&31)*64, ld NDIM   (pairs x plane2)
//   c in [64,80): Bq   col (c&15)*64, ld MMID   (pairs u plane1)
//   c in [80,96): Bq2  col (c&15)*64, ld MMID   (pairs u plane2)
//   epilogue: q8 -> fp32 outp + fp16 aux
// MODE 1 (GEMM2): B = P0 col (c&31)*64, ld NDIM; epilogue q8 -> fp32 outp.
// nchunk must be a multiple of 4 (96 and 32 are).
// ----------------------------------------------------------------------------
#define NSTAGE 3
#define BKE 64
#define TILE 128
#define TILE_BYTES (TILE * 128)                 // 16 KB per operand
#define STAGE_BYTES (2 * TILE_BYTES)            // 32 KB
#define SMEM_SZ (NSTAGE * STAGE_BYTES)          // 96 KB

template <int MODE>
__global__ void __launch_bounds__(256, 1)
mma_gemm(const __half* __restrict__ Aop, int ldA, int nchunk,
         const __half* __restrict__ P0, const __half* __restrict__ P1,
         const __half* __restrict__ P2, const __half* __restrict__ P3,
         float* __restrict__ outp, __half* __restrict__ aux, int ldOut)
{
    extern __shared__ char smem[];
    const uint32_t sb = smem_u32(smem);
    const int tid  = threadIdx.x;
    const int lane = tid & 31;
    const int wid  = tid >> 5;
    const int wm   = wid & 1;    // 2 m-slices of 64
    const int wn   = wid >> 1;   // 4 n-slices of 32
    const int m0 = blockIdx.y * TILE;
    const int n0 = blockIdx.x * TILE;

    const int lr  = tid >> 1;
    const int lc0 = (tid & 1) * 4;

    auto load_chunk = [&](int c) {
        const int s = c % NSTAGE;
        const uint32_t sA = sb + s * STAGE_BYTES;
        const uint32_t sB = sA + TILE_BYTES;
        const __half* arow = Aop + (size_t)(m0 + lr) * ldA + c * BKE;
        const __half* bsrc; int ldB;
        if (MODE == 0) {
            if (c < 64) { bsrc = ((c < 32) ? P0 : P1) + (size_t)(c & 31) * BKE; ldB = NDIM; }
            else        { bsrc = ((c < 80) ? P2 : P3) + (size_t)(c & 15) * BKE; ldB = MMID; }
        } else {
            bsrc = P0 + (size_t)(c & 31) * BKE; ldB = NDIM;
        }
        const __half* brow = bsrc + (size_t)(n0 + lr) * ldB;
#pragma unroll
        for (int j = 0; j < 4; j++) {
            int c16 = lc0 + j;
            uint32_t off = swz(lr * 128 + c16 * 16);
            cp16(sA + off, arow + c16 * 8);
            cp16(sB + off, brow + c16 * 8);
        }
        cp_commit();
    };

    float mst[4][4][4];   // master fp32 accumulator (RN adds)
    float acc[4][4][4];   // HMMA chain accumulator (short chains only)
#pragma unroll
    for (int i = 0; i < 4; i++)
#pragma unroll
        for (int j = 0; j < 4; j++)
#pragma unroll
            for (int k = 0; k < 4; k++) mst[i][j][k] = 0.0f;

    load_chunk(0);
    load_chunk(1);

    for (int c = 0; c < nchunk; c++) {
        asm volatile("cp.async.wait_group 1;" ::: "memory");
        __syncthreads();

        if (c + 2 < nchunk) load_chunk(c + 2);
        else                cp_commit();        // keep group accounting uniform

        const int s = c % NSTAGE;
        const uint32_t sA = sb + s * STAGE_BYTES;
        const uint32_t sB = sA + TILE_BYTES;

        if ((c & 3) == 0) {                      // start a fresh HMMA chain
#pragma unroll
            for (int i = 0; i < 4; i++)
#pragma unroll
                for (int j = 0; j < 4; j++)
#pragma unroll
                    for (int k = 0; k < 4; k++) acc[i][j][k] = 0.0f;
        }

#pragma unroll
        for (int ks = 0; ks < 4; ks++) {        // 4 x k16 per 64-chunk
            uint32_t af[4][4];
#pragma unroll
            for (int mt = 0; mt < 4; mt++) {
                int row = wm * 64 + mt * 16 + ((lane >> 3) & 1) * 8 + (lane & 7);
                int ku  = ks * 2 + (lane >> 4);
                ldsm4(af[mt][0], af[mt][1], af[mt][2], af[mt][3],
                      sA + swz(row * 128 + ku * 16));
            }
            uint32_t bf[2][4];
#pragma unroll
            for (int np = 0; np < 2; np++) {
                int row = wn * 32 + np * 16 + (lane >> 4) * 8 + (lane & 7);
                int ku  = ks * 2 + ((lane >> 3) & 1);
                ldsm4(bf[np][0], bf[np][1], bf[np][2], bf[np][3],
                      sB + swz(row * 128 + ku * 16));
            }
#pragma unroll
            for (int mt = 0; mt < 4; mt++)
#pragma unroll
                for (int nt = 0; nt < 4; nt++)
                    mma16816(acc[mt][nt], af[mt], &bf[nt >> 1][(nt & 1) * 2]);
        }

        if ((c & 3) == 3) {                      // flush chain into master (RN)
#pragma unroll
            for (int i = 0; i < 4; i++)
#pragma unroll
                for (int j = 0; j < 4; j++)
#pragma unroll
                    for (int k = 0; k < 4; k++) mst[i][j][k] += acc[i][j][k];
        }
    }

    // Epilogue: q8 then direct stores
#pragma unroll
    for (int mt = 0; mt < 4; mt++) {
#pragma unroll
        for (int nt = 0; nt < 4; nt++) {
            int row0 = m0 + wm * 64 + mt * 16 + (lane >> 2);
            int col  = n0 + wn * 32 + nt * 8 + 2 * (lane & 3);
#pragma unroll
            for (int h = 0; h < 2; h++) {
                int row = row0 + h * 8;
                float v0 = q8(mst[mt][nt][h * 2 + 0]);
                float v1 = q8(mst[mt][nt][h * 2 + 1]);
                size_t g = (size_t)row * ldOut + col;
                *reinterpret_cast<float2*>(outp + g) = make_float2(v0, v1);
                if (MODE == 0) {
                    __half2 hv = __floats2half2_rn(v0, v1);
                    *reinterpret_cast<__half2*>(aux + g) = hv;
                }
            }
        }
    }
}

// ----------------------------------------------------------------------------
// Host launcher
// ----------------------------------------------------------------------------
extern "C" void kernel_launch(void* const* d_in, const int* in_sizes, int n_in,
                              void* d_out, int out_size)
{
    const float* x = (const float*)d_in[0];
    const float* u = (const float*)d_in[1];
    const float* A = (const float*)d_in[2];
    const float* B = (const float*)d_in[3];
    const float* C = (const float*)d_in[4];

    float* x_next = (float*)d_out;
    float* y      = (float*)d_out + (size_t)MDIM * NDIM;

    __half *Aq, *Aq2, *Bq, *Bq2, *Cq, *XU, *Xn;
    cudaGetSymbolAddress((void**)&Aq,  g_Aq);
    cudaGetSymbolAddress((void**)&Aq2, g_Aq2);
    cudaGetSymbolAddress((void**)&Bq,  g_Bq);
    cudaGetSymbolAddress((void**)&Bq2, g_Bq2);
    cudaGetSymbolAddress((void**)&Cq,  g_Cq);
    cudaGetSymbolAddress((void**)&XU,  g_XU);
    cudaGetSymbolAddress((void**)&Xn,  g_Xn);

    cudaFuncSetAttribute(mma_gemm<0>, cudaFuncAttributeMaxDynamicSharedMemorySize, SMEM_SZ);
    cudaFuncSetAttribute(mma_gemm<1>, cudaFuncAttributeMaxDynamicSharedMemorySize, SMEM_SZ);

    const int T = 256;
    quantq<<<(NDIM * NDIM / 4 + T - 1) / T, T>>>(A, Aq, Aq2, NDIM * NDIM);
    quantq<<<(NDIM * MMID / 4 + T - 1) / T, T>>>(B, Bq, Bq2, NDIM * MMID);
    quantq<<<(MMID * NDIM / 4 + T - 1) / T, T>>>(C, Cq, (__half*)nullptr, MMID * NDIM);
    splitk<<<(int)(((size_t)MDIM * NDIM / 4 + T - 1) / T), T>>>(x, NDIM, XU);
    splitk<<<(int)(((size_t)MDIM * MMID / 4 + T - 1) / T), T>>>(u, MMID, XU + 2 * NDIM);

    // fused GEMM1: x_next = q8(XU @ [Aq | Aq/64 | Bq | Bq/64]^T), K=6144 (96 chunks)
    {
        dim3 grid(NDIM / TILE, MDIM / TILE);   // (16, 32)
        mma_gemm<0><<<grid, 256, SMEM_SZ>>>(
            XU, KEFF, KEFF / BKE,
            Aq, Aq2, Bq, Bq2,
            x_next, Xn, NDIM);
    }
    // GEMM2: y = q8(Xn @ Cq^T), K=2048 (32 chunks)
    {
        dim3 grid(MMID / TILE, MDIM / TILE);   // (8, 32)
        mma_gemm<1><<<grid, 256, SMEM_SZ>>>(
            Xn, NDIM, NDIM / BKE,
            Cq, (const __half*)nullptr, (const __half*)nullptr, (const __half*)nullptr,
            y, (__half*)nullptr, MMID);
    }
}

// round 6
// speedup vs baseline: 3.3380x; 1.0413x over previous
#include <cuda_runtime.h>
#include <cuda_fp16.h>
#include <math.h>
#include <stdint.h>

// ============================================================================
// QuantizedSSM via mma.sync (HMMA) with chunked fp32 re-accumulation.
// HMMA internal accumulation rounds toward zero -> flush into a master fp32
// accumulator (RN) every 4 chunks (256 k-elements).
//   x_next = q8( x @ Aq^T + u @ Bq^T ) : fused fp16 GEMM, K = 6144
//   y      = q8( x_next @ Cq^T )       : exact fp16 GEMM, K = 2048
// R6: paired-chunk smem stages (2 chunks / stage) -> half the barriers,
//     double the prefetch depth (4 chunks in flight).
// ============================================================================

#define MDIM 4096
#define NDIM 2048
#define MMID 1024
#define KEFF (2*NDIM + 2*MMID)   // 6144

__device__ __half g_Aq [(size_t)NDIM * NDIM];
__device__ __half g_Aq2[(size_t)NDIM * NDIM];   // Aq / 64
__device__ __half g_Bq [(size_t)NDIM * MMID];
__device__ __half g_Bq2[(size_t)NDIM * MMID];   // Bq / 64
__device__ __half g_Cq [(size_t)MMID * NDIM];
__device__ __half g_XU [(size_t)MDIM * KEFF];   // [x1 | x2*64 | u1 | u2*64]
__device__ __half g_Xn [(size_t)MDIM * NDIM];   // x_next fp16 (exact)

// ----------------------------------------------------------------------------
// q8 = to_float8(v, 4, 3), branch-free bit version (exact vs reference).
// ----------------------------------------------------------------------------
__device__ __forceinline__ float q8(float v) {
    float a  = fabsf(v);
    float ae = a + 1e-8f;
    int e = ((__float_as_int(ae) >> 23) & 0xFF) - 127;
    e = min(max(e, -7), 7);
    float p  = __int_as_float((e + 127) << 23);   // 2^e
    float rp = __int_as_float((127 - e) << 23);   // 2^-e (exact)
    float m  = fmaf(a, rp, -1.0f);
    float mq = rintf(m * 8.0f);                   // round-half-even == jnp.round
    float r  = fmaf(mq, 0.125f, 1.0f) * p;
    return (v > 0.0f) ? r : ((v < 0.0f) ? -r : 0.0f);
}

// ----------------------------------------------------------------------------
// PTX helpers — all plain-target (sm_80+) instructions
// ----------------------------------------------------------------------------
__device__ __forceinline__ uint32_t smem_u32(const void* p) {
    uint32_t a;
    asm("{ .reg .u64 t; cvta.to.shared.u64 t, %1; cvt.u32.u64 %0, t; }"
        : "=r"(a) : "l"(p));
    return a;
}
__device__ __forceinline__ void cp16(uint32_t dst, const void* src) {
    asm volatile("cp.async.cg.shared.global [%0], [%1], 16;"
                 :: "r"(dst), "l"(src) : "memory");
}
__device__ __forceinline__ void cp_commit() {
    asm volatile("cp.async.commit_group;" ::: "memory");
}
__device__ __forceinline__ void ldsm4(uint32_t& r0, uint32_t& r1, uint32_t& r2,
                                      uint32_t& r3, uint32_t addr) {
    asm volatile("ldmatrix.sync.aligned.m8n8.x4.shared.b16 {%0,%1,%2,%3}, [%4];"
                 : "=r"(r0), "=r"(r1), "=r"(r2), "=r"(r3) : "r"(addr));
}
__device__ __forceinline__ void mma16816(float* d, const uint32_t* a, const uint32_t* b) {
    asm volatile(
        "mma.sync.aligned.m16n8k16.row.col.f32.f16.f16.f32 "
        "{%0,%1,%2,%3}, {%4,%5,%6,%7}, {%8,%9}, {%0,%1,%2,%3};"
        : "+f"(d[0]), "+f"(d[1]), "+f"(d[2]), "+f"(d[3])
        : "r"(a[0]), "r"(a[1]), "r"(a[2]), "r"(a[3]), "r"(b[0]), "r"(b[1]));
}

// SW128 swizzle (Swizzle<3,4,3>) on byte offsets within a 128B-row tile
__device__ __forceinline__ uint32_t swz(uint32_t o) { return o ^ ((o >> 3) & 0x70); }

// ----------------------------------------------------------------------------
// Prep kernels
// ----------------------------------------------------------------------------
__global__ void quantq(const float* __restrict__ in, __half* __restrict__ out,
                       __half* __restrict__ out2, int n) {
    size_t i = ((size_t)blockIdx.x * blockDim.x + threadIdx.x) * 4;
    if (i >= (size_t)n) return;
    float4 v = *reinterpret_cast<const float4*>(in + i);
    float q0 = q8(v.x), q1 = q8(v.y), q2 = q8(v.z), q3 = q8(v.w);
    __half2 p0 = __floats2half2_rn(q0, q1);
    __half2 p1 = __floats2half2_rn(q2, q3);
    uint2 pk;
    pk.x = *reinterpret_cast<uint32_t*>(&p0);
    pk.y = *reinterpret_cast<uint32_t*>(&p1);
    *reinterpret_cast<uint2*>(out + i) = pk;
    if (out2) {
        const float s = 0.015625f;  // 1/64, exact scaling
        __half2 s0 = __floats2half2_rn(q0 * s, q1 * s);
        __half2 s1 = __floats2half2_rn(q2 * s, q3 * s);
        uint2 sk;
        sk.x = *reinterpret_cast<uint32_t*>(&s0);
        sk.y = *reinterpret_cast<uint32_t*>(&s1);
        *reinterpret_cast<uint2*>(out2 + i) = sk;
    }
}

// split fp32 -> plane1 = fp16(v) at [col], plane2 = fp16((v-plane1)*64) at [col+cols]
__global__ void splitk(const float* __restrict__ src, int cols, __half* __restrict__ dst) {
    size_t idx = (size_t)blockIdx.x * blockDim.x + threadIdx.x;
    size_t i4 = idx * 4;
    if (i4 >= (size_t)MDIM * cols) return;
    int row = (int)(i4 / cols);
    int col = (int)(i4 % cols);
    float4 v = *reinterpret_cast<const float4*>(src + i4);
    float f[4] = {v.x, v.y, v.z, v.w};
    __half h1[4], h2[4];
#pragma unroll
    for (int j = 0; j < 4; j++) {
        __half b1 = __float2half_rn(f[j]);
        float r1 = f[j] - __half2float(b1);   // exact in fp32
        h1[j] = b1;
        h2[j] = __float2half_rn(r1 * 64.0f);  // scaled into normal fp16 range
    }
    __half* d0 = dst + (size_t)row * KEFF + col;
    auto pack = [](__half* h) {
        __half2 p0(h[0], h[1]), p1(h[2], h[3]);
        uint2 r;
        r.x = *reinterpret_cast<uint32_t*>(&p0);
        r.y = *reinterpret_cast<uint32_t*>(&p1);
        return r;
    };
    *reinterpret_cast<uint2*>(d0)        = pack(h1);
    *reinterpret_cast<uint2*>(d0 + cols) = pack(h2);
}

// ----------------------------------------------------------------------------
// HMMA GEMM-NT, 128x128 CTA tile, BK=64, paired-chunk 3-stage pipeline.
// Each smem stage holds 2 chunks (A0,B0,A1,B1 = 64KB); one barrier per pair.
// MODE 0 (fused GEMM1): chunk c -> B segment
//   c in [ 0,32): Aq   col (c&31)*64, ld NDIM   (pairs x plane1)
//   c in [32,64): Aq2  col (c&31)*64, ld NDIM   (pairs x plane2)
//   c in [64,80): Bq   col (c&15)*64, ld MMID   (pairs u plane1)
//   c in [80,96): Bq2  col (c&15)*64, ld MMID   (pairs u plane2)
//   epilogue: q8 -> fp32 outp + fp16 aux
// MODE 1 (GEMM2): B = P0 col (c&31)*64, ld NDIM; epilogue q8 -> fp32 outp.
// nchunk must be a multiple of 4 (96 and 32 are).
// ----------------------------------------------------------------------------
#define NSTAGE 3
#define BKE 64
#define TILE 128
#define TILE_BYTES (TILE * 128)                 // 16 KB per operand-chunk
#define STAGE_BYTES (4 * TILE_BYTES)            // 64 KB: A0,B0,A1,B1
#define SMEM_SZ (NSTAGE * STAGE_BYTES)          // 192 KB

template <int MODE>
__global__ void __launch_bounds__(256, 1)
mma_gemm(const __half* __restrict__ Aop, int ldA, int nchunk,
         const __half* __restrict__ P0, const __half* __restrict__ P1,
         const __half* __restrict__ P2, const __half* __restrict__ P3,
         float* __restrict__ outp, __half* __restrict__ aux, int ldOut)
{
    extern __shared__ char smem[];
    const uint32_t sb = smem_u32(smem);
    const int tid  = threadIdx.x;
    const int lane = tid & 31;
    const int wid  = tid >> 5;
    const int wm   = wid & 1;    // 2 m-slices of 64
    const int wn   = wid >> 1;   // 4 n-slices of 32
    const int m0 = blockIdx.y * TILE;
    const int n0 = blockIdx.x * TILE;

    const int lr  = tid >> 1;
    const int lc0 = (tid & 1) * 4;

    // load one 64-k chunk into half-stage (q = 0/1 within pair)
    auto load_chunk = [&](int c, uint32_t base) {
        const uint32_t sA = base;
        const uint32_t sB = base + TILE_BYTES;
        const __half* arow = Aop + (size_t)(m0 + lr) * ldA + c * BKE;
        const __half* bsrc; int ldB;
        if (MODE == 0) {
            if (c < 64) { bsrc = ((c < 32) ? P0 : P1) + (size_t)(c & 31) * BKE; ldB = NDIM; }
            else        { bsrc = ((c < 80) ? P2 : P3) + (size_t)(c & 15) * BKE; ldB = MMID; }
        } else {
            bsrc = P0 + (size_t)(c & 31) * BKE; ldB = NDIM;
        }
        const __half* brow = bsrc + (size_t)(n0 + lr) * ldB;
#pragma unroll
        for (int j = 0; j < 4; j++) {
            int c16 = lc0 + j;
            uint32_t off = swz(lr * 128 + c16 * 16);
            cp16(sA + off, arow + c16 * 8);
            cp16(sB + off, brow + c16 * 8);
        }
    };
    auto load_pair = [&](int p) {
        const uint32_t base = sb + (p % NSTAGE) * STAGE_BYTES;
        load_chunk(2 * p,     base);
        load_chunk(2 * p + 1, base + 2 * TILE_BYTES);
        cp_commit();
    };

    float mst[4][4][4];   // master fp32 accumulator (RN adds)
    float acc[4][4][4];   // HMMA chain accumulator (short chains only)
#pragma unroll
    for (int i = 0; i < 4; i++)
#pragma unroll
        for (int j = 0; j < 4; j++)
#pragma unroll
            for (int k = 0; k < 4; k++) mst[i][j][k] = 0.0f;

    // compute one chunk from smem half-stage
    auto compute_chunk = [&](uint32_t sA, uint32_t sB) {
#pragma unroll
        for (int ks = 0; ks < 4; ks++) {        // 4 x k16 per 64-chunk
            uint32_t af[4][4];
#pragma unroll
            for (int mt = 0; mt < 4; mt++) {
                int row = wm * 64 + mt * 16 + ((lane >> 3) & 1) * 8 + (lane & 7);
                int ku  = ks * 2 + (lane >> 4);
                ldsm4(af[mt][0], af[mt][1], af[mt][2], af[mt][3],
                      sA + swz(row * 128 + ku * 16));
            }
            uint32_t bf[2][4];
#pragma unroll
            for (int np = 0; np < 2; np++) {
                int row = wn * 32 + np * 16 + (lane >> 4) * 8 + (lane & 7);
                int ku  = ks * 2 + ((lane >> 3) & 1);
                ldsm4(bf[np][0], bf[np][1], bf[np][2], bf[np][3],
                      sB + swz(row * 128 + ku * 16));
            }
#pragma unroll
            for (int mt = 0; mt < 4; mt++)
#pragma unroll
                for (int nt = 0; nt < 4; nt++)
                    mma16816(acc[mt][nt], af[mt], &bf[nt >> 1][(nt & 1) * 2]);
        }
    };

    const int npairs = nchunk / 2;
    load_pair(0);
    load_pair(1);

    for (int p = 0; p < npairs; p++) {
        asm volatile("cp.async.wait_group 1;" ::: "memory");
        __syncthreads();

        if (p + 2 < npairs) load_pair(p + 2);
        else                cp_commit();        // keep group accounting uniform

        const uint32_t base = sb + (p % NSTAGE) * STAGE_BYTES;

        // chunk 2p
        if (((2 * p) & 3) == 0) {                // start fresh HMMA chain
#pragma unroll
            for (int i = 0; i < 4; i++)
#pragma unroll
                for (int j = 0; j < 4; j++)
#pragma unroll
                    for (int k = 0; k < 4; k++) acc[i][j][k] = 0.0f;
        }
        compute_chunk(base, base + TILE_BYTES);

        // chunk 2p+1 (never a chain start: chain starts are even chunks)
        compute_chunk(base + 2 * TILE_BYTES, base + 3 * TILE_BYTES);

        if (((2 * p + 1) & 3) == 3) {            // flush chain into master (RN)
#pragma unroll
            for (int i = 0; i < 4; i++)
#pragma unroll
                for (int j = 0; j < 4; j++)
#pragma unroll
                    for (int k = 0; k < 4; k++) mst[i][j][k] += acc[i][j][k];
        }
    }

    // Epilogue: q8 then direct stores
#pragma unroll
    for (int mt = 0; mt < 4; mt++) {
#pragma unroll
        for (int nt = 0; nt < 4; nt++) {
            int row0 = m0 + wm * 64 + mt * 16 + (lane >> 2);
            int col  = n0 + wn * 32 + nt * 8 + 2 * (lane & 3);
#pragma unroll
            for (int h = 0; h < 2; h++) {
                int row = row0 + h * 8;
                float v0 = q8(mst[mt][nt][h * 2 + 0]);
                float v1 = q8(mst[mt][nt][h * 2 + 1]);
                size_t g = (size_t)row * ldOut + col;
                *reinterpret_cast<float2*>(outp + g) = make_float2(v0, v1);
                if (MODE == 0) {
                    __half2 hv = __floats2half2_rn(v0, v1);
                    *reinterpret_cast<__half2*>(aux + g) = hv;
                }
            }
        }
    }
}

// ----------------------------------------------------------------------------
// Host launcher
// ----------------------------------------------------------------------------
extern "C" void kernel_launch(void* const* d_in, const int* in_sizes, int n_in,
                              void* d_out, int out_size)
{
    const float* x = (const float*)d_in[0];
    const float* u = (const float*)d_in[1];
    const float* A = (const float*)d_in[2];
    const float* B = (const float*)d_in[3];
    const float* C = (const float*)d_in[4];

    float* x_next = (float*)d_out;
    float* y      = (float*)d_out + (size_t)MDIM * NDIM;

    __half *Aq, *Aq2, *Bq, *Bq2, *Cq, *XU, *Xn;
    cudaGetSymbolAddress((void**)&Aq,  g_Aq);
    cudaGetSymbolAddress((void**)&Aq2, g_Aq2);
    cudaGetSymbolAddress((void**)&Bq,  g_Bq);
    cudaGetSymbolAddress((void**)&Bq2, g_Bq2);
    cudaGetSymbolAddress((void**)&Cq,  g_Cq);
    cudaGetSymbolAddress((void**)&XU,  g_XU);
    cudaGetSymbolAddress((void**)&Xn,  g_Xn);

    cudaFuncSetAttribute(mma_gemm<0>, cudaFuncAttributeMaxDynamicSharedMemorySize, SMEM_SZ);
    cudaFuncSetAttribute(mma_gemm<1>, cudaFuncAttributeMaxDynamicSharedMemorySize, SMEM_SZ);

    const int T = 256;
    quantq<<<(NDIM * NDIM / 4 + T - 1) / T, T>>>(A, Aq, Aq2, NDIM * NDIM);
    quantq<<<(NDIM * MMID / 4 + T - 1) / T, T>>>(B, Bq, Bq2, NDIM * MMID);
    quantq<<<(MMID * NDIM / 4 + T - 1) / T, T>>>(C, Cq, (__half*)nullptr, MMID * NDIM);
    splitk<<<(int)(((size_t)MDIM * NDIM / 4 + T - 1) / T), T>>>(x, NDIM, XU);
    splitk<<<(int)(((size_t)MDIM * MMID / 4 + T - 1) / T), T>>>(u, MMID, XU + 2 * NDIM);

    // fused GEMM1: x_next = q8(XU @ [Aq | Aq/64 | Bq | Bq/64]^T), K=6144 (96 chunks)
    {
        dim3 grid(NDIM / TILE, MDIM / TILE);   // (16, 32)
        mma_gemm<0><<<grid, 256, SMEM_SZ>>>(
            XU, KEFF, KEFF / BKE,
            Aq, Aq2, Bq, Bq2,
            x_next, Xn, NDIM);
    }
    // GEMM2: y = q8(Xn @ Cq^T), K=2048 (32 chunks)
    {
        dim3 grid(MMID / TILE, MDIM / TILE);   // (8, 32)
        mma_gemm<1><<<grid, 256, SMEM_SZ>>>(
            Xn, NDIM, NDIM / BKE,
            Cq, (const __half*)nullptr, (const __half*)nullptr, (const __half*)nullptr,
            y, (__half*)nullptr, MMID);
    }
}

// round 7
// speedup vs baseline: 3.6472x; 1.0926x over previous
#include <cuda_runtime.h>
#include <cuda_fp16.h>
#include <math.h>
#include <stdint.h>

// ============================================================================
// QuantizedSSM via mma.sync (HMMA) with chunked fp32 re-accumulation.
// HMMA internal accumulation rounds toward zero -> flush into a master fp32
// accumulator (RN) every 4 chunks (256 k-elements).
//   x_next = q8( x @ Aq^T + u @ Bq^T ) : fused fp16 GEMM, K = 6144
//   y      = q8( x_next @ Cq^T )       : exact fp16 GEMM, K = 2048
// R7: 128x64 CTA tiles -> ~110 regs/thread -> 2 CTAs/SM, so barriers and
//     ldsm->mma bubbles in one CTA overlap the other CTA's HMMA work.
//     4 single-chunk smem stages, wait_group 2 (3 chunks in flight).
// ============================================================================

#define MDIM 4096
#define NDIM 2048
#define MMID 1024
#define KEFF (2*NDIM + 2*MMID)   // 6144

__device__ __half g_Aq [(size_t)NDIM * NDIM];
__device__ __half g_Aq2[(size_t)NDIM * NDIM];   // Aq / 64
__device__ __half g_Bq [(size_t)NDIM * MMID];
__device__ __half g_Bq2[(size_t)NDIM * MMID];   // Bq / 64
__device__ __half g_Cq [(size_t)MMID * NDIM];
__device__ __half g_XU [(size_t)MDIM * KEFF];   // [x1 | x2*64 | u1 | u2*64]
__device__ __half g_Xn [(size_t)MDIM * NDIM];   // x_next fp16 (exact)

// ----------------------------------------------------------------------------
// q8 = to_float8(v, 4, 3), branch-free bit version (exact vs reference).
// ----------------------------------------------------------------------------
__device__ __forceinline__ float q8(float v) {
    float a  = fabsf(v);
    float ae = a + 1e-8f;
    int e = ((__float_as_int(ae) >> 23) & 0xFF) - 127;
    e = min(max(e, -7), 7);
    float p  = __int_as_float((e + 127) << 23);   // 2^e
    float rp = __int_as_float((127 - e) << 23);   // 2^-e (exact)
    float m  = fmaf(a, rp, -1.0f);
    float mq = rintf(m * 8.0f);                   // round-half-even == jnp.round
    float r  = fmaf(mq, 0.125f, 1.0f) * p;
    return (v > 0.0f) ? r : ((v < 0.0f) ? -r : 0.0f);
}

// ----------------------------------------------------------------------------
// PTX helpers — all plain-target (sm_80+) instructions
// ----------------------------------------------------------------------------
__device__ __forceinline__ uint32_t smem_u32(const void* p) {
    uint32_t a;
    asm("{ .reg .u64 t; cvta.to.shared.u64 t, %1; cvt.u32.u64 %0, t; }"
        : "=r"(a) : "l"(p));
    return a;
}
__device__ __forceinline__ void cp16(uint32_t dst, const void* src) {
    asm volatile("cp.async.cg.shared.global [%0], [%1], 16;"
                 :: "r"(dst), "l"(src) : "memory");
}
__device__ __forceinline__ void cp_commit() {
    asm volatile("cp.async.commit_group;" ::: "memory");
}
__device__ __forceinline__ void ldsm4(uint32_t& r0, uint32_t& r1, uint32_t& r2,
                                      uint32_t& r3, uint32_t addr) {
    asm volatile("ldmatrix.sync.aligned.m8n8.x4.shared.b16 {%0,%1,%2,%3}, [%4];"
                 : "=r"(r0), "=r"(r1), "=r"(r2), "=r"(r3) : "r"(addr));
}
__device__ __forceinline__ void mma16816(float* d, const uint32_t* a, const uint32_t* b) {
    asm volatile(
        "mma.sync.aligned.m16n8k16.row.col.f32.f16.f16.f32 "
        "{%0,%1,%2,%3}, {%4,%5,%6,%7}, {%8,%9}, {%0,%1,%2,%3};"
        : "+f"(d[0]), "+f"(d[1]), "+f"(d[2]), "+f"(d[3])
        : "r"(a[0]), "r"(a[1]), "r"(a[2]), "r"(a[3]), "r"(b[0]), "r"(b[1]));
}

// SW128 swizzle (Swizzle<3,4,3>) on byte offsets within a 128B-row tile
__device__ __forceinline__ uint32_t swz(uint32_t o) { return o ^ ((o >> 3) & 0x70); }

// ----------------------------------------------------------------------------
// Prep kernels
// ----------------------------------------------------------------------------
__global__ void quantq(const float* __restrict__ in, __half* __restrict__ out,
                       __half* __restrict__ out2, int n) {
    size_t i = ((size_t)blockIdx.x * blockDim.x + threadIdx.x) * 4;
    if (i >= (size_t)n) return;
    float4 v = *reinterpret_cast<const float4*>(in + i);
    float q0 = q8(v.x), q1 = q8(v.y), q2 = q8(v.z), q3 = q8(v.w);
    __half2 p0 = __floats2half2_rn(q0, q1);
    __half2 p1 = __floats2half2_rn(q2, q3);
    uint2 pk;
    pk.x = *reinterpret_cast<uint32_t*>(&p0);
    pk.y = *reinterpret_cast<uint32_t*>(&p1);
    *reinterpret_cast<uint2*>(out + i) = pk;
    if (out2) {
        const float s = 0.015625f;  // 1/64, exact scaling
        __half2 s0 = __floats2half2_rn(q0 * s, q1 * s);
        __half2 s1 = __floats2half2_rn(q2 * s, q3 * s);
        uint2 sk;
        sk.x = *reinterpret_cast<uint32_t*>(&s0);
        sk.y = *reinterpret_cast<uint32_t*>(&s1);
        *reinterpret_cast<uint2*>(out2 + i) = sk;
    }
}

// split fp32 -> plane1 = fp16(v) at [col], plane2 = fp16((v-plane1)*64) at [col+cols]
__global__ void splitk(const float* __restrict__ src, int cols, __half* __restrict__ dst) {
    size_t idx = (size_t)blockIdx.x * blockDim.x + threadIdx.x;
    size_t i4 = idx * 4;
    if (i4 >= (size_t)MDIM * cols) return;
    int row = (int)(i4 / cols);
    int col = (int)(i4 % cols);
    float4 v = *reinterpret_cast<const float4*>(src + i4);
    float f[4] = {v.x, v.y, v.z, v.w};
    __half h1[4], h2[4];
#pragma unroll
    for (int j = 0; j < 4; j++) {
        __half b1 = __float2half_rn(f[j]);
        float r1 = f[j] - __half2float(b1);   // exact in fp32
        h1[j] = b1;
        h2[j] = __float2half_rn(r1 * 64.0f);  // scaled into normal fp16 range
    }
    __half* d0 = dst + (size_t)row * KEFF + col;
    auto pack = [](__half* h) {
        __half2 p0(h[0], h[1]), p1(h[2], h[3]);
        uint2 r;
        r.x = *reinterpret_cast<uint32_t*>(&p0);
        r.y = *reinterpret_cast<uint32_t*>(&p1);
        return r;
    };
    *reinterpret_cast<uint2*>(d0)        = pack(h1);
    *reinterpret_cast<uint2*>(d0 + cols) = pack(h2);
}

// ----------------------------------------------------------------------------
// HMMA GEMM-NT, 128x64 CTA tile, BK=64, 4-stage single-chunk pipeline.
// 8 warps: wm = wid&3 (4 x 32 rows), wn = wid>>2 (2 x 32 cols).
// MODE 0 (fused GEMM1): chunk c -> B segment
//   c in [ 0,32): Aq   col (c&31)*64, ld NDIM   (pairs x plane1)
//   c in [32,64): Aq2  col (c&31)*64, ld NDIM   (pairs x plane2)
//   c in [64,80): Bq   col (c&15)*64, ld MMID   (pairs u plane1)
//   c in [80,96): Bq2  col (c&15)*64, ld MMID   (pairs u plane2)
//   epilogue: q8 -> fp32 outp + fp16 aux
// MODE 1 (GEMM2): B = P0 col (c&31)*64, ld NDIM; epilogue q8 -> fp32 outp.
// nchunk must be a multiple of 4 (96 and 32 are).
// ----------------------------------------------------------------------------
#define NSTAGE 4
#define BKE 64
#define TILEM 128
#define TILEN 64
#define A_BYTES (TILEM * 128)                   // 16 KB
#define B_BYTES (TILEN * 128)                   //  8 KB
#define STAGE_BYTES (A_BYTES + B_BYTES)         // 24 KB
#define SMEM_SZ (NSTAGE * STAGE_BYTES)          // 96 KB

template <int MODE>
__global__ void __launch_bounds__(256, 2)
mma_gemm(const __half* __restrict__ Aop, int ldA, int nchunk,
         const __half* __restrict__ P0, const __half* __restrict__ P1,
         const __half* __restrict__ P2, const __half* __restrict__ P3,
         float* __restrict__ outp, __half* __restrict__ aux, int ldOut)
{
    extern __shared__ char smem[];
    const uint32_t sb = smem_u32(smem);
    const int tid  = threadIdx.x;
    const int lane = tid & 31;
    const int wid  = tid >> 5;
    const int wm   = wid & 3;    // 4 m-slices of 32
    const int wn   = wid >> 2;   // 2 n-slices of 32
    const int m0 = blockIdx.y * TILEM;
    const int n0 = blockIdx.x * TILEN;

    // A: 128 rows, 2 threads/row, 4 x 16B each.  B: 64 rows, 4 threads/row, 2 x 16B.
    const int alr  = tid >> 1;
    const int alc0 = (tid & 1) * 4;
    const int blr  = tid >> 2;
    const int blc0 = (tid & 3) * 2;

    auto load_chunk = [&](int c) {
        const uint32_t sA = sb + (c % NSTAGE) * STAGE_BYTES;
        const uint32_t sB = sA + A_BYTES;
        const __half* arow = Aop + (size_t)(m0 + alr) * ldA + c * BKE;
        const __half* bsrc; int ldB;
        if (MODE == 0) {
            if (c < 64) { bsrc = ((c < 32) ? P0 : P1) + (size_t)(c & 31) * BKE; ldB = NDIM; }
            else        { bsrc = ((c < 80) ? P2 : P3) + (size_t)(c & 15) * BKE; ldB = MMID; }
        } else {
            bsrc = P0 + (size_t)(c & 31) * BKE; ldB = NDIM;
        }
        const __half* brow = bsrc + (size_t)(n0 + blr) * ldB;
#pragma unroll
        for (int j = 0; j < 4; j++) {
            int c16 = alc0 + j;
            cp16(sA + swz(alr * 128 + c16 * 16), arow + c16 * 8);
        }
#pragma unroll
        for (int j = 0; j < 2; j++) {
            int c16 = blc0 + j;
            cp16(sB + swz(blr * 128 + c16 * 16), brow + c16 * 8);
        }
        cp_commit();
    };

    float mst[2][4][4];   // master fp32 accumulator (RN adds)
    float acc[2][4][4];   // HMMA chain accumulator (short chains only)
#pragma unroll
    for (int i = 0; i < 2; i++)
#pragma unroll
        for (int j = 0; j < 4; j++)
#pragma unroll
            for (int k = 0; k < 4; k++) mst[i][j][k] = 0.0f;

    auto compute_chunk = [&](uint32_t sA, uint32_t sB) {
#pragma unroll
        for (int ks = 0; ks < 4; ks++) {        // 4 x k16 per 64-chunk
            uint32_t af[2][4];
#pragma unroll
            for (int mt = 0; mt < 2; mt++) {
                int row = wm * 32 + mt * 16 + ((lane >> 3) & 1) * 8 + (lane & 7);
                int ku  = ks * 2 + (lane >> 4);
                ldsm4(af[mt][0], af[mt][1], af[mt][2], af[mt][3],
                      sA + swz(row * 128 + ku * 16));
            }
            uint32_t bf[2][4];
#pragma unroll
            for (int np = 0; np < 2; np++) {
                int row = wn * 32 + np * 16 + (lane >> 4) * 8 + (lane & 7);
                int ku  = ks * 2 + ((lane >> 3) & 1);
                ldsm4(bf[np][0], bf[np][1], bf[np][2], bf[np][3],
                      sB + swz(row * 128 + ku * 16));
            }
#pragma unroll
            for (int mt = 0; mt < 2; mt++)
#pragma unroll
                for (int nt = 0; nt < 4; nt++)
                    mma16816(acc[mt][nt], af[mt], &bf[nt >> 1][(nt & 1) * 2]);
        }
    };

    load_chunk(0);
    load_chunk(1);
    load_chunk(2);

    for (int c = 0; c < nchunk; c++) {
        asm volatile("cp.async.wait_group 2;" ::: "memory");
        __syncthreads();

        if (c + 3 < nchunk) load_chunk(c + 3);
        else                cp_commit();        // keep group accounting uniform

        const uint32_t sA = sb + (c % NSTAGE) * STAGE_BYTES;

        if ((c & 3) == 0) {                      // start fresh HMMA chain
#pragma unroll
            for (int i = 0; i < 2; i++)
#pragma unroll
                for (int j = 0; j < 4; j++)
#pragma unroll
                    for (int k = 0; k < 4; k++) acc[i][j][k] = 0.0f;
        }

        compute_chunk(sA, sA + A_BYTES);

        if ((c & 3) == 3) {                      // flush chain into master (RN)
#pragma unroll
            for (int i = 0; i < 2; i++)
#pragma unroll
                for (int j = 0; j < 4; j++)
#pragma unroll
                    for (int k = 0; k < 4; k++) mst[i][j][k] += acc[i][j][k];
        }
    }

    // Epilogue: q8 then direct stores
#pragma unroll
    for (int mt = 0; mt < 2; mt++) {
#pragma unroll
        for (int nt = 0; nt < 4; nt++) {
            int row0 = m0 + wm * 32 + mt * 16 + (lane >> 2);
            int col  = n0 + wn * 32 + nt * 8 + 2 * (lane & 3);
#pragma unroll
            for (int h = 0; h < 2; h++) {
                int row = row0 + h * 8;
                float v0 = q8(mst[mt][nt][h * 2 + 0]);
                float v1 = q8(mst[mt][nt][h * 2 + 1]);
                size_t g = (size_t)row * ldOut + col;
                *reinterpret_cast<float2*>(outp + g) = make_float2(v0, v1);
                if (MODE == 0) {
                    __half2 hv = __floats2half2_rn(v0, v1);
                    *reinterpret_cast<__half2*>(aux + g) = hv;
                }
            }
        }
    }
}

// ----------------------------------------------------------------------------
// Host launcher
// ----------------------------------------------------------------------------
extern "C" void kernel_launch(void* const* d_in, const int* in_sizes, int n_in,
                              void* d_out, int out_size)
{
    const float* x = (const float*)d_in[0];
    const float* u = (const float*)d_in[1];
    const float* A = (const float*)d_in[2];
    const float* B = (const float*)d_in[3];
    const float* C = (const float*)d_in[4];

    float* x_next = (float*)d_out;
    float* y      = (float*)d_out + (size_t)MDIM * NDIM;

    __half *Aq, *Aq2, *Bq, *Bq2, *Cq, *XU, *Xn;
    cudaGetSymbolAddress((void**)&Aq,  g_Aq);
    cudaGetSymbolAddress((void**)&Aq2, g_Aq2);
    cudaGetSymbolAddress((void**)&Bq,  g_Bq);
    cudaGetSymbolAddress((void**)&Bq2, g_Bq2);
    cudaGetSymbolAddress((void**)&Cq,  g_Cq);
    cudaGetSymbolAddress((void**)&XU,  g_XU);
    cudaGetSymbolAddress((void**)&Xn,  g_Xn);

    cudaFuncSetAttribute(mma_gemm<0>, cudaFuncAttributeMaxDynamicSharedMemorySize, SMEM_SZ);
    cudaFuncSetAttribute(mma_gemm<1>, cudaFuncAttributeMaxDynamicSharedMemorySize, SMEM_SZ);

    const int T = 256;
    quantq<<<(NDIM * NDIM / 4 + T - 1) / T, T>>>(A, Aq, Aq2, NDIM * NDIM);
    quantq<<<(NDIM * MMID / 4 + T - 1) / T, T>>>(B, Bq, Bq2, NDIM * MMID);
    quantq<<<(MMID * NDIM / 4 + T - 1) / T, T>>>(C, Cq, (__half*)nullptr, MMID * NDIM);
    splitk<<<(int)(((size_t)MDIM * NDIM / 4 + T - 1) / T), T>>>(x, NDIM, XU);
    splitk<<<(int)(((size_t)MDIM * MMID / 4 + T - 1) / T), T>>>(u, MMID, XU + 2 * NDIM);

    // fused GEMM1: x_next = q8(XU @ [Aq | Aq/64 | Bq | Bq/64]^T), K=6144 (96 chunks)
    {
        dim3 grid(NDIM / TILEN, MDIM / TILEM);   // (32, 32)
        mma_gemm<0><<<grid, 256, SMEM_SZ>>>(
            XU, KEFF, KEFF / BKE,
            Aq, Aq2, Bq, Bq2,
            x_next, Xn, NDIM);
    }
    // GEMM2: y = q8(Xn @ Cq^T), K=2048 (32 chunks)
    {
        dim3 grid(MMID / TILEN, MDIM / TILEM);   // (16, 32)
        mma_gemm<1><<<grid, 256, SMEM_SZ>>>(
            Xn, NDIM, NDIM / BKE,
            Cq, (const __half*)nullptr, (const __half*)nullptr, (const __half*)nullptr,
            y, (__half*)nullptr, MMID);
    }
}